// round 16
// baseline (speedup 1.0000x reference)
#include <cuda_runtime.h>
#include <cuda_fp16.h>
#include <cstdint>

#define NN 50000
#define RR 16
#define HH 64
#define CC 16
#define EE 800000
#define CAP 32   // max edges per (dst, relation) bucket; counts ~Poisson(1), max ~10

typedef unsigned int u32;
typedef unsigned long long u64;

// ---------------- device scratch (static; no allocation) ----------------
__device__ u32   g_bin[(size_t)NN * RR * CAP]; // src ids bucketed by (dst, rel), 102.4 MB
__device__ int   g_cnt[NN * RR];               // edge counts per (dst, relation)
__device__ float g_X1[(size_t)NN * HH];        // hidden layer activations (fp32)

__device__ __forceinline__ u32 smem_u32(const void* p) {
    u32 a;
    asm("{ .reg .u64 t; cvta.to.shared.u64 t, %1; cvt.u32.u64 %0, t; }" : "=r"(a) : "l"(p));
    return a;
}

// ldmatrix x4 (sm_75+; compiles at plain sm_103)
__device__ __forceinline__ void ldm4(u32* d, u32 addr) {
    asm volatile("ldmatrix.sync.aligned.m8n8.x4.shared.b16 {%0,%1,%2,%3}, [%4];"
                 : "=r"(d[0]), "=r"(d[1]), "=r"(d[2]), "=r"(d[3]) : "r"(addr));
}

// classic HMMA fp16 -> f32 accumulate (sm_80+)
__device__ __forceinline__ void mma16816(float* d, const u32* a, u32 b0, u32 b1) {
    asm volatile("mma.sync.aligned.m16n8k16.row.col.f32.f16.f16.f32 "
                 "{%0,%1,%2,%3}, {%4,%5,%6,%7}, {%8,%9}, {%0,%1,%2,%3};"
                 : "+f"(d[0]), "+f"(d[1]), "+f"(d[2]), "+f"(d[3])
                 : "r"(a[0]), "r"(a[1]), "r"(a[2]), "r"(a[3]), "r"(b0), "r"(b1));
}

// ---------------- binning kernels (shared by both layers) ----------------
__global__ void zero_cnt_k() {
    int i = blockIdx.x * blockDim.x + threadIdx.x;
    if (i < NN * RR) g_cnt[i] = 0;
}

__global__ void fill_k(const int* __restrict__ ei, const int* __restrict__ et) {
    int e = blockIdx.x * blockDim.x + threadIdx.x;
    if (e < EE) {
        int src = ei[e];
        int dst = ei[EE + e];
        int r   = et[e];
        int b   = dst * RR + r;
        int pos = atomicAdd(&g_cnt[b], 1);
        if (pos < CAP) g_bin[(size_t)b * CAP + pos] = (u32)src;
    }
}

// ---------------- HMMA GEMM with in-kernel gather-reduce A-prep ----------------
// out = maybe_relu( [mean_gather | root_input] @ [W ; rootW] + bias )
// A-prep chunk t<16: for node v, gather x[src] over bucket (v, t), fp32
// accumulate, scale by 1/cnt, round ONCE to fp16. Chunk 16 = root input.
// B: f16/f16 split (Wh + Wl). D += A*Wh + A*Wl, fp32 accumulation.
// M=NN (BM=128, 8 warps x 16 rows), N=OUTD, K=1088 (17 chunks of 64).
template <int OUTD, bool RELU, bool USE_X1, bool OUT_X1>
__global__ __launch_bounds__(256) void gemm_mma(const float* __restrict__ xin,
                                                const float* __restrict__ W,
                                                const float* __restrict__ rootW,
                                                const float* __restrict__ bias,
                                                float* __restrict__ outp) {
    constexpr int AP = 72;                 // f16 pitch: 144B rows, conflict-free ldmatrix
    extern __shared__ __half sm[];
    __half* Ahs = sm;                      // 128 x AP
    __half* Bh  = Ahs + 128 * AP;          // OUTD x AP
    __half* Bl  = Bh + OUTD * AP;          // OUTD x AP

    int tid = threadIdx.x;
    int wid = tid >> 5, lane = tid & 31;
    int g = lane >> 3, r = lane & 7;
    int v0 = blockIdx.x * 128;

    const float* gsrc = USE_X1 ? g_X1 : xin;   // gather source (and root input)

    u32 sb = smem_u32(sm);
    u32 a_base = sb + ((u32)((wid * 16 + (g & 1) * 8 + r) * AP + (g >> 1) * 8)) * 2;
    u32 bh_base = sb + 128 * AP * 2 + ((u32)(((g >> 1) * 8 + r) * AP + (g & 1) * 8)) * 2;
    u32 bl_base = bh_base + OUTD * AP * 2;

    // A-prep mapping: 2 threads per node, 32 consecutive features each
    int pnode = tid >> 1;
    int phalf = tid & 1;

    float acc[OUTD / 8][4];
    #pragma unroll
    for (int i = 0; i < OUTD / 8; ++i)
        #pragma unroll
        for (int j = 0; j < 4; ++j) acc[i][j] = 0.f;

    for (int t = 0; t < 17; ++t) {
        // ---- A tile prep ----
        if (t < 16) {
            // gather-reduce over bucket (v, t) in fp32, one fp16 rounding
            float af[32];
            #pragma unroll
            for (int q = 0; q < 32; ++q) af[q] = 0.f;
            int v = v0 + pnode;
            int cnt = 0;
            if (v < NN) {
                int b = v * RR + t;
                cnt = g_cnt[b];
                const u32* bp = &g_bin[(size_t)b * CAP];
                for (int i = 0; i < cnt; ++i) {
                    const float4* xs = (const float4*)&gsrc[(size_t)bp[i] * 64 + phalf * 32];
                    #pragma unroll
                    for (int q = 0; q < 8; ++q) {
                        float4 w = xs[q];
                        af[q * 4 + 0] += w.x;
                        af[q * 4 + 1] += w.y;
                        af[q * 4 + 2] += w.z;
                        af[q * 4 + 3] += w.w;
                    }
                }
            }
            float inv = (cnt > 0) ? 1.0f / (float)cnt : 0.0f;
            #pragma unroll
            for (int q8 = 0; q8 < 4; ++q8) {
                __half2 m0 = __floats2half2_rn(af[q8 * 8 + 0] * inv, af[q8 * 8 + 1] * inv);
                __half2 m1 = __floats2half2_rn(af[q8 * 8 + 2] * inv, af[q8 * 8 + 3] * inv);
                __half2 m2 = __floats2half2_rn(af[q8 * 8 + 4] * inv, af[q8 * 8 + 5] * inv);
                __half2 m3 = __floats2half2_rn(af[q8 * 8 + 6] * inv, af[q8 * 8 + 7] * inv);
                *(uint4*)&Ahs[pnode * AP + phalf * 32 + q8 * 8] =
                    make_uint4(*(u32*)&m0, *(u32*)&m1, *(u32*)&m2, *(u32*)&m3);
            }
        } else {
            // root chunk: fp32 input -> fp16
            #pragma unroll
            for (int i = 0; i < 4; ++i) {
                int idx = tid + i * 256;      // 8-float units, 0..1023
                int node = idx >> 3, kq = idx & 7;
                int v = v0 + node;
                float4 a4 = make_float4(0.f, 0.f, 0.f, 0.f);
                float4 b4 = make_float4(0.f, 0.f, 0.f, 0.f);
                if (v < NN) {
                    a4 = *(const float4*)&gsrc[(size_t)v * 64 + kq * 8];
                    b4 = *(const float4*)&gsrc[(size_t)v * 64 + kq * 8 + 4];
                }
                __half2 m0 = __floats2half2_rn(a4.x, a4.y);
                __half2 m1 = __floats2half2_rn(a4.z, a4.w);
                __half2 m2 = __floats2half2_rn(b4.x, b4.y);
                __half2 m3 = __floats2half2_rn(b4.z, b4.w);
                *(uint4*)&Ahs[node * AP + kq * 8] =
                    make_uint4(*(u32*)&m0, *(u32*)&m1, *(u32*)&m2, *(u32*)&m3);
            }
        }
        // ---- B tile prep: transpose [64 k][OUTD n] fp32 -> Bs[n][k], f16 hi/lo split ----
        {
            const float4* Bsrc = (t < 16) ? (const float4*)(W + (size_t)t * 64 * OUTD)
                                          : (const float4*)rootW;
            constexpr int NF4 = 64 * OUTD / 4;
            #pragma unroll
            for (int i = 0; i < NF4 / 256; ++i) {
                int idx = tid + i * 256;
                int k = idx / (OUTD / 4), nq = idx % (OUTD / 4);
                float4 w4 = Bsrc[idx];
                float f[4] = {w4.x, w4.y, w4.z, w4.w};
                #pragma unroll
                for (int j = 0; j < 4; ++j) {
                    int n = nq * 4 + j;
                    __half h = __float2half_rn(f[j]);
                    Bh[n * AP + k] = h;
                    Bl[n * AP + k] = __float2half_rn(f[j] - __half2float(h));
                }
            }
        }
        __syncthreads();
        // ---- MMA: 4 k-steps x (OUTD/16) n-blocks x 2 split terms ----
        #pragma unroll
        for (int ks = 0; ks < 4; ++ks) {
            u32 a[4];
            ldm4(a, a_base + ks * 32);
            #pragma unroll
            for (int nb = 0; nb < OUTD / 16; ++nb) {
                u32 bh[4], bl[4];
                ldm4(bh, bh_base + ks * 32 + nb * (16 * AP * 2));
                ldm4(bl, bl_base + ks * 32 + nb * (16 * AP * 2));
                mma16816(acc[nb * 2],     a, bh[0], bh[1]);
                mma16816(acc[nb * 2 + 1], a, bh[2], bh[3]);
                mma16816(acc[nb * 2],     a, bl[0], bl[1]);
                mma16816(acc[nb * 2 + 1], a, bl[2], bl[3]);
            }
        }
        __syncthreads();
    }

    // ---- epilogue: bias (+relu), direct fragment store ----
    float* dst = OUT_X1 ? g_X1 : outp;     // device-side symbol reference (ATS pitfall!)
    int row0 = v0 + wid * 16 + (lane >> 2);
    int colb = (lane & 3) * 2;
    #pragma unroll
    for (int ns = 0; ns < OUTD / 8; ++ns) {
        int col = ns * 8 + colb;
        float bx = bias[col], by = bias[col + 1];
        float o0 = acc[ns][0] + bx, o1 = acc[ns][1] + by;
        float o2 = acc[ns][2] + bx, o3 = acc[ns][3] + by;
        if (RELU) {
            o0 = fmaxf(o0, 0.f); o1 = fmaxf(o1, 0.f);
            o2 = fmaxf(o2, 0.f); o3 = fmaxf(o3, 0.f);
        }
        if (row0 < NN)
            *(float2*)&dst[(size_t)row0 * OUTD + col] = make_float2(o0, o1);
        if (row0 + 8 < NN)
            *(float2*)&dst[(size_t)(row0 + 8) * OUTD + col] = make_float2(o2, o3);
    }
}

// ---------------- launch ----------------
extern "C" void kernel_launch(void* const* d_in, const int* in_sizes, int n_in,
                              void* d_out, int out_size) {
    const int*   ei    = (const int*)d_in[0];
    const int*   et    = (const int*)d_in[1];
    const float* x     = (const float*)d_in[2];
    const float* W1    = (const float*)d_in[3];
    const float* root1 = (const float*)d_in[4];
    const float* b1    = (const float*)d_in[5];
    const float* W2    = (const float*)d_in[6];
    const float* root2 = (const float*)d_in[7];
    const float* b2    = (const float*)d_in[8];
    float* out = (float*)d_out;

    (void)in_sizes; (void)n_in; (void)out_size;

    constexpr int AP = 72;
    const int SMEM1 = (128 + 2 * 64) * AP * 2;   // 36864 B
    const int SMEM2 = (128 + 2 * 16) * AP * 2;   // 23040 B
    cudaFuncSetAttribute(gemm_mma<64, true, false, true>,
                         cudaFuncAttributeMaxDynamicSharedMemorySize, SMEM1);
    cudaFuncSetAttribute(gemm_mma<16, false, true, false>,
                         cudaFuncAttributeMaxDynamicSharedMemorySize, SMEM2);

    const int GB = (NN + 127) / 128;

    // ---- edge binning (shared by both layers) ----
    zero_cnt_k<<<(NN * RR + 255) / 256, 256>>>();
    fill_k<<<(EE + 255) / 256, 256>>>(ei, et);

    // ---- layer 1 ----
    gemm_mma<64, true, false, true><<<GB, 256, SMEM1>>>(x, W1, root1, b1, nullptr);

    // ---- layer 2 ----
    gemm_mma<16, false, true, false><<<GB, 256, SMEM2>>>(nullptr, W2, root2, b2, out);
}